// round 11
// baseline (speedup 1.0000x reference)
#include <cuda_runtime.h>
#include <cuda_fp16.h>
#include <cuda_pipeline.h>
#include <mma.h>
#include <math.h>

using namespace nvcuda;

#define TT 2048
#define DD 1024
#define NH 8
#define HD 128
#define GATE_IN 12

#define ATTN_SCALE 0.12f
#define RMS_EPS 1e-6f
#define LOG2E 1.4426950408889634f
#define SOFT_SHIFT 8.0f

static __device__ float  g_qkv[(size_t)TT * 3 * DD];  // [t][3*D]
static __device__ __half g_wh[(size_t)4 * DD * DD];   // weight hi
static __device__ __half g_wl[(size_t)4 * DD * DD];   // weight lo
static __device__ __half g_xh[(size_t)TT * DD];       // x hi
static __device__ __half g_xl[(size_t)TT * DD];       // x lo
static __device__ __half g_yh[(size_t)TT * DD];       // y hi
static __device__ __half g_yl[(size_t)TT * DD];       // y lo
static __device__ __half g_qh[(size_t)NH * TT * HD];  // scaled q hi
static __device__ __half g_ql[(size_t)NH * TT * HD];  // scaled q lo
static __device__ __half g_kh[(size_t)NH * TT * HD];  // k hi
static __device__ __half g_kl[(size_t)NH * TT * HD];  // k lo
static __device__ __half g_vh[(size_t)NH * TT * HD];  // v half

// ---------------------------------------------------------------------------
// split f32 -> (hi, lo) f16 pairs for both w and x in one launch.
// chunk = one float4. w chunks first, then x chunks.
// ---------------------------------------------------------------------------
__device__ __forceinline__ void split4(const float* __restrict__ src, size_t i,
                                       __half* __restrict__ dh,
                                       __half* __restrict__ dl)
{
    float4 v = ((const float4*)src)[i];
    __half h0 = __float2half_rn(v.x), h1 = __float2half_rn(v.y);
    __half h2 = __float2half_rn(v.z), h3 = __float2half_rn(v.w);
    __half2* dh2 = (__half2*)dh;
    __half2* dl2 = (__half2*)dl;
    dh2[i * 2]     = __halves2half2(h0, h1);
    dh2[i * 2 + 1] = __halves2half2(h2, h3);
    dl2[i * 2]     = __halves2half2(__float2half_rn(v.x - __half2float(h0)),
                                    __float2half_rn(v.y - __half2float(h1)));
    dl2[i * 2 + 1] = __halves2half2(__float2half_rn(v.z - __half2float(h2)),
                                    __float2half_rn(v.w - __half2float(h3)));
}

#define WCHUNKS (4 * DD * DD / 4)
#define XCHUNKS (TT * DD / 4)

__global__ void split_all_kernel(const float* __restrict__ w,
                                 const float* __restrict__ x)
{
    size_t i = (size_t)blockIdx.x * blockDim.x + threadIdx.x;
    if (i < WCHUNKS) {
        split4(w, i, g_wh, g_wl);
    } else {
        split4(x, i - WCHUNKS, g_xh, g_xl);
    }
}

// ---------------------------------------------------------------------------
// f16x3 GEMM on pre-split halves, 2-stage cp.async pipeline.
// C[m][n] = sum_k A[m][k]*W[n][k].  Block 64x128, BK=16, 128 thr = 4 warps
// (2x2, warp tile 32x64).  D = ah*bh + al*bh + ah*bl.
// MODE 0: A = g_xh/g_xl, B = W[0:3D], C = g_qkv.
// MODE 1: A = g_yh/g_yl, B = W[3D:4D], C = out.
// ---------------------------------------------------------------------------
template <int MODE>
__global__ void __launch_bounds__(128) gemm_presplit_kernel(
    float* __restrict__ Cext, int M, int N, int K)
{
    const __half* __restrict__ Ahp = (MODE == 0) ? g_xh : g_yh;
    const __half* __restrict__ Alp = (MODE == 0) ? g_xl : g_yl;
    const __half* __restrict__ Bhp = g_wh + (MODE == 0 ? 0 : (size_t)3 * DD * DD);
    const __half* __restrict__ Blp = g_wl + (MODE == 0 ? 0 : (size_t)3 * DD * DD);
    float* __restrict__ C = (MODE == 0) ? (float*)g_qkv : Cext;

    __shared__ __half Ah[2][64][24];
    __shared__ __half Al[2][64][24];
    __shared__ __half Bh[2][128][24];
    __shared__ __half Bl[2][128][24];

    const int tid = threadIdx.x;
    const int warp = tid >> 5;
    const int wm = warp >> 1;       // 0..1
    const int wn = warp & 1;        // 0..1
    const int bm = blockIdx.y * 64, bn = blockIdx.x * 128;

    // per-thread async loader for one k-tile into stage s
    const int arr = tid >> 1, ac8 = (tid & 1) * 8;

    wmma::fragment<wmma::accumulator, 16, 16, 16, float> acc[2][4];
#pragma unroll
    for (int mt = 0; mt < 2; mt++)
#pragma unroll
        for (int nt = 0; nt < 4; nt++)
            wmma::fill_fragment(acc[mt][nt], 0.0f);

    const int nk = K / 16;

    // prologue: stage 0
    {
        size_t go = (size_t)(bm + arr) * K + ac8;
        __pipeline_memcpy_async(&Ah[0][arr][ac8], Ahp + go, 16);
        __pipeline_memcpy_async(&Al[0][arr][ac8], Alp + go, 16);
#pragma unroll
        for (int i = 0; i < 2; i++) {
            int idx = tid + i * 128;
            int rr = idx >> 1, c8 = (idx & 1) * 8;
            size_t gob = (size_t)(bn + rr) * K + c8;
            __pipeline_memcpy_async(&Bh[0][rr][c8], Bhp + gob, 16);
            __pipeline_memcpy_async(&Bl[0][rr][c8], Blp + gob, 16);
        }
        __pipeline_commit();
    }

    for (int it = 0; it < nk; it++) {
        if (it + 1 < nk) {
            const int s = (it + 1) & 1;
            const int kt = (it + 1) * 16;
            size_t go = (size_t)(bm + arr) * K + kt + ac8;
            __pipeline_memcpy_async(&Ah[s][arr][ac8], Ahp + go, 16);
            __pipeline_memcpy_async(&Al[s][arr][ac8], Alp + go, 16);
#pragma unroll
            for (int i = 0; i < 2; i++) {
                int idx = tid + i * 128;
                int rr = idx >> 1, c8 = (idx & 1) * 8;
                size_t gob = (size_t)(bn + rr) * K + kt + c8;
                __pipeline_memcpy_async(&Bh[s][rr][c8], Bhp + gob, 16);
                __pipeline_memcpy_async(&Bl[s][rr][c8], Blp + gob, 16);
            }
            __pipeline_commit();
            __pipeline_wait_prior(1);
        } else {
            __pipeline_wait_prior(0);
        }
        __syncthreads();

        const int s = it & 1;
        wmma::fragment<wmma::matrix_a, 16, 16, 16, __half,
                       wmma::row_major> fah[2], fal[2];
#pragma unroll
        for (int mt = 0; mt < 2; mt++) {
            wmma::load_matrix_sync(fah[mt], &Ah[s][wm * 32 + mt * 16][0], 24);
            wmma::load_matrix_sync(fal[mt], &Al[s][wm * 32 + mt * 16][0], 24);
        }
#pragma unroll
        for (int nt = 0; nt < 4; nt++) {
            wmma::fragment<wmma::matrix_b, 16, 16, 16, __half,
                           wmma::col_major> fbh, fbl;
            wmma::load_matrix_sync(fbh, &Bh[s][wn * 64 + nt * 16][0], 24);
            wmma::load_matrix_sync(fbl, &Bl[s][wn * 64 + nt * 16][0], 24);
#pragma unroll
            for (int mt = 0; mt < 2; mt++) {
                wmma::mma_sync(acc[mt][nt], fah[mt], fbh, acc[mt][nt]);
                wmma::mma_sync(acc[mt][nt], fal[mt], fbh, acc[mt][nt]);
                wmma::mma_sync(acc[mt][nt], fah[mt], fbl, acc[mt][nt]);
            }
        }
        __syncthreads();
    }

#pragma unroll
    for (int mt = 0; mt < 2; mt++)
#pragma unroll
        for (int nt = 0; nt < 4; nt++) {
            float* cp = C + (size_t)(bm + wm * 32 + mt * 16) * N
                          + bn + wn * 64 + nt * 16;
            wmma::store_matrix_sync(cp, acc[mt][nt], N, wmma::mem_row_major);
        }
}

// ---------------------------------------------------------------------------
// Postprocess: per (t,h): rms_norm + rotary on q,k; v = l0*v + l1*ve.
// Emits pre-scaled f16 hi/lo splits for q (scale*log2e folded) and k, v half.
// ---------------------------------------------------------------------------
__global__ void postproc_kernel(const float* __restrict__ ve,
                                const float* __restrict__ lam,
                                const float* __restrict__ cosb,
                                const float* __restrict__ sinb)
{
    const int t = blockIdx.x >> 3;
    const int h = blockIdx.x & 7;
    const int hd = threadIdx.x;

    const float* rowp = g_qkv + (size_t)t * (3 * DD) + h * HD;
    float qv = rowp[hd];
    float kv = rowp[DD + hd];
    float vv = rowp[2 * DD + hd];

    float sq = qv * qv, sk = kv * kv;
#pragma unroll
    for (int o = 16; o; o >>= 1) {
        sq += __shfl_xor_sync(0xffffffffu, sq, o);
        sk += __shfl_xor_sync(0xffffffffu, sk, o);
    }
    __shared__ float red[2][4];
    int w = hd >> 5, lane = hd & 31;
    if (lane == 0) { red[0][w] = sq; red[1][w] = sk; }
    __syncthreads();
    sq = red[0][0] + red[0][1] + red[0][2] + red[0][3];
    sk = red[1][0] + red[1][1] + red[1][2] + red[1][3];
    float qr = rsqrtf(sq * (1.0f / HD) + RMS_EPS);
    float kr = rsqrtf(sk * (1.0f / HD) + RMS_EPS);

    __shared__ float qn[HD], kn[HD];
    qn[hd] = qv * qr;
    kn[hd] = kv * kr;
    __syncthreads();

    float qo, ko;
    if (hd < 64) {
        float cc = cosb[t * 64 + hd];
        float ss = sinb[t * 64 + hd];
        qo = qn[hd] * cc + qn[hd + 64] * ss;
        ko = kn[hd] * cc + kn[hd + 64] * ss;
    } else {
        int j = hd - 64;
        float cc = cosb[t * 64 + j];
        float ss = sinb[t * 64 + j];
        qo = -qn[j] * ss + qn[hd] * cc;
        ko = -kn[j] * ss + kn[hd] * cc;
    }
    const float lm0 = __ldg(lam);
    const float lm1 = __ldg(lam + 1);
    size_t oidx = ((size_t)h * TT + t) * HD + hd;

    float qs = qo * (ATTN_SCALE * LOG2E);
    __half qhh = __float2half_rn(qs);
    g_qh[oidx] = qhh;
    g_ql[oidx] = __float2half_rn(qs - __half2float(qhh));
    __half khh = __float2half_rn(ko);
    g_kh[oidx] = khh;
    g_kl[oidx] = __float2half_rn(ko - __half2float(khh));
    float vo = lm0 * vv + lm1 * ve[((size_t)t * NH + h) * HD + hd];
    g_vh[oidx] = __float2half_rn(vo);
}

// ---------------------------------------------------------------------------
// Flash attention, all-f16 wmma, cp.async pipelined.
// Grid (32, 8), 128 threads = 4 warps; warp owns 16 q rows; key tiles of 32.
// K-hi double buffered in smem; V single-buffered (load overlaps QK+softmax);
// K-lo and Q-lo fragments direct from global (L1). QK: 3-term f16 split.
// Softmax fixed shift exp2(s-8); O never rescaled. PV half wmma.
// Epilogue emits y as (hi, lo) halves.
// ---------------------------------------------------------------------------
__global__ void __launch_bounds__(128) flash_wmma_kernel(
    const float* __restrict__ x, const float* __restrict__ gate_w)
{
    // smem (bytes):
    //   0     : Khs[2] 2 x 32x136 half = 17408
    //   17408 : Vsm 32x136 half = 8704
    //   26112 : Ssm per warp 16x36 f32 (2304 ea x4) = 9216
    //   35328 : Psm per warp 16x40 half (1280 ea x4) = 5120
    //   total 40448.  Epilogue reuses [0..33792) as per-warp 16x132 f32.
    __shared__ __align__(16) unsigned char smraw[40448];
    __half (*Khs)[32][136] = (__half (*)[32][136])(smraw);
    __half (*Vsm)[136]     = (__half (*)[136])(smraw + 17408);

    const int h = blockIdx.y;
    const int qb = (int)gridDim.x - 1 - (int)blockIdx.x;   // heavy tiles first
    const int tid = threadIdx.x, warp = tid >> 5, lane = tid & 31;
    const int qbase = qb * 64;
    const int wrow0 = qbase + warp * 16;
    const int myrow = lane >> 1;
    const int myhalf = lane & 1;
    const int grow = wrow0 + myrow;

    float  (*Ssm_w)[36] = (float  (*)[36])(smraw + 26112 + warp * 2304);
    __half (*Psm_w)[40] = (__half (*)[40])(smraw + 35328 + warp * 1280);

    const __half* Qhp = g_qh + (size_t)h * TT * HD;
    const __half* Qlp = g_ql + (size_t)h * TT * HD;
    const __half* Khp = g_kh + (size_t)h * TT * HD;
    const __half* Klp = g_kl + (size_t)h * TT * HD;
    const __half* Vp  = g_vh + (size_t)h * TT * HD;

    wmma::fragment<wmma::matrix_a, 16, 16, 16, __half, wmma::row_major> qhf[8];
#pragma unroll
    for (int kt = 0; kt < 8; kt++)
        wmma::load_matrix_sync(qhf[kt], Qhp + (size_t)wrow0 * HD + kt * 16, HD);

    wmma::fragment<wmma::accumulator, 16, 16, 16, float> oacc[8];
#pragma unroll
    for (int nt = 0; nt < 8; nt++) wmma::fill_fragment(oacc[nt], 0.0f);
    float lrun = 0.0f;

    const int nkb = 2 * qb + 2;

    // prologue: K tile 0 -> stage 0
#pragma unroll
    for (int i = 0; i < 4; i++) {
        int idx = tid + i * 128;
        int rr = idx >> 4, c8 = (idx & 15) * 8;
        __pipeline_memcpy_async(&Khs[0][rr][c8],
                                Khp + (size_t)rr * HD + c8, 16);
    }
    __pipeline_commit();

    for (int kb = 0; kb < nkb; kb++) {
        const int kbase = kb * 32;
        const bool more = (kb + 1 < nkb);

        // issue V(kb)
#pragma unroll
        for (int i = 0; i < 4; i++) {
            int idx = tid + i * 128;
            int rr = idx >> 4, c8 = (idx & 15) * 8;
            __pipeline_memcpy_async(&Vsm[rr][c8],
                                    Vp + (size_t)(kbase + rr) * HD + c8, 16);
        }
        __pipeline_commit();
        // issue K(kb+1)
        if (more) {
            const int s = (kb + 1) & 1;
            const int kb2 = kbase + 32;
#pragma unroll
            for (int i = 0; i < 4; i++) {
                int idx = tid + i * 128;
                int rr = idx >> 4, c8 = (idx & 15) * 8;
                __pipeline_memcpy_async(&Khs[s][rr][c8],
                                        Khp + (size_t)(kb2 + rr) * HD + c8, 16);
            }
            __pipeline_commit();
            __pipeline_wait_prior(2);   // K(kb) ready
        } else {
            __pipeline_wait_prior(1);   // K(kb) ready
        }
        __syncthreads();

        const bool active = (kbase <= wrow0 + 15);   // warp-uniform
        const int s = kb & 1;
        if (active) {
            wmma::fragment<wmma::accumulator, 16, 16, 16, float> sacc[2];
            wmma::fill_fragment(sacc[0], 0.0f);
            wmma::fill_fragment(sacc[1], 0.0f);
#pragma unroll
            for (int kt = 0; kt < 8; kt++) {
                wmma::fragment<wmma::matrix_a, 16, 16, 16, __half,
                               wmma::row_major> qlf;
                wmma::load_matrix_sync(qlf, Qlp + (size_t)wrow0 * HD + kt * 16, HD);
#pragma unroll
                for (int nt = 0; nt < 2; nt++) {
                    wmma::fragment<wmma::matrix_b, 16, 16, 16, __half,
                                   wmma::col_major> khf, klf;
                    wmma::load_matrix_sync(khf, &Khs[s][nt * 16][kt * 16], 136);
                    wmma::load_matrix_sync(klf,
                        Klp + (size_t)(kbase + nt * 16) * HD + kt * 16, HD);
                    wmma::mma_sync(sacc[nt], qhf[kt], khf, sacc[nt]);
                    wmma::mma_sync(sacc[nt], qlf,     khf, sacc[nt]);
                    wmma::mma_sync(sacc[nt], qhf[kt], klf, sacc[nt]);
                }
            }
            wmma::store_matrix_sync(&Ssm_w[0][0],  sacc[0], 36, wmma::mem_row_major);
            wmma::store_matrix_sync(&Ssm_w[0][16], sacc[1], 36, wmma::mem_row_major);
        }
        __syncwarp();
        if (active) {
            float lsum = 0.0f;
#pragma unroll
            for (int j = 0; j < 16; j++) {
                int col = myhalf * 16 + j;
                int gcol = kbase + col;
                float sv = Ssm_w[myrow][col];
                float p = (gcol <= grow) ? exp2f(sv - SOFT_SHIFT) : 0.0f;
                lsum += p;
                Psm_w[myrow][col] = __float2half(p);
            }
            lsum += __shfl_xor_sync(0xffffffffu, lsum, 1);
            lrun += lsum;
        }
        __syncwarp();

        // V(kb) must be resident before PV
        if (more) __pipeline_wait_prior(1);
        else      __pipeline_wait_prior(0);
        __syncthreads();

        if (active) {
#pragma unroll
            for (int ks = 0; ks < 2; ks++) {
                wmma::fragment<wmma::matrix_a, 16, 16, 16,
                               __half, wmma::row_major> pfrag;
                wmma::load_matrix_sync(pfrag, &Psm_w[0][ks * 16], 40);
#pragma unroll
                for (int nt = 0; nt < 8; nt++) {
                    wmma::fragment<wmma::matrix_b, 16, 16, 16,
                                   __half, wmma::row_major> vfrag;
                    wmma::load_matrix_sync(vfrag, &Vsm[ks * 16][nt * 16], 136);
                    wmma::mma_sync(oacc[nt], pfrag, vfrag, oacc[nt]);
                }
            }
        }
        __syncthreads();
    }

    // epilogue: stage O to smem, normalize, gate, emit (hi, lo) halves
    float (*Osm_w)[132] = (float (*)[132])(smraw + warp * 8448);
#pragma unroll
    for (int nt = 0; nt < 8; nt++)
        wmma::store_matrix_sync(&Osm_w[0][nt * 16], oacc[nt], 132,
                                wmma::mem_row_major);
    __syncwarp();

    float gd = 0.0f;
#pragma unroll
    for (int i = 0; i < GATE_IN; i++)
        gd += x[(size_t)grow * DD + i] * gate_w[h * GATE_IN + i];
    float gate = 1.0f / (1.0f + expf(-gd));
    float scale = gate / lrun;

    const int c0 = myhalf * 64;
    __half* yh = g_yh + (size_t)grow * DD + h * HD;
    __half* yl = g_yl + (size_t)grow * DD + h * HD;
#pragma unroll
    for (int j = 0; j < 16; j++) {
        float4 ov = *(float4*)&Osm_w[myrow][c0 + j * 4];
        float v0 = ov.x * scale, v1 = ov.y * scale;
        float v2 = ov.z * scale, v3 = ov.w * scale;
        __half h0 = __float2half_rn(v0), h1 = __float2half_rn(v1);
        __half h2 = __float2half_rn(v2), h3 = __float2half_rn(v3);
        __half2* yh2 = (__half2*)(yh + c0 + j * 4);
        yh2[0] = __halves2half2(h0, h1);
        yh2[1] = __halves2half2(h2, h3);
        __half2* yl2 = (__half2*)(yl + c0 + j * 4);
        yl2[0] = __halves2half2(__float2half_rn(v0 - __half2float(h0)),
                                __float2half_rn(v1 - __half2float(h1)));
        yl2[1] = __halves2half2(__float2half_rn(v2 - __half2float(h2)),
                                __float2half_rn(v3 - __half2float(h3)));
    }
}

// ---------------------------------------------------------------------------
extern "C" void kernel_launch(void* const* d_in, const int* in_sizes, int n_in,
                              void* d_out, int out_size)
{
    const float* x      = (const float*)d_in[0];  // (1,2048,1024)
    const float* qkvo_w = (const float*)d_in[1];  // (4,1024,1024)
    const float* gate_w = (const float*)d_in[2];  // (8,12)
    const float* ve     = (const float*)d_in[3];  // (1,2048,8,128)
    const float* lam    = (const float*)d_in[4];  // (2,)
    const float* cosb   = (const float*)d_in[5];  // (2048,64)
    const float* sinb   = (const float*)d_in[6];  // (2048,64)
    float* out = (float*)d_out;                   // (1,2048,1024)

    // 0) pre-split weights and x into f16 (hi, lo) in one launch
    split_all_kernel<<<(WCHUNKS + XCHUNKS) / 256, 256>>>(qkvo_w, x);

    // 1) QKV projection -> g_qkv
    {
        dim3 grid(3072 / 128, 2048 / 64);
        gemm_presplit_kernel<0><<<grid, 128>>>(nullptr, TT, 3 * DD, DD);
    }
    // 2) rms_norm + rotary + value mix + split
    postproc_kernel<<<TT * NH, 128>>>(ve, lam, cosb, sinb);
    // 3) causal flash attention + gate -> g_yh/g_yl
    {
        dim3 grid(TT / 64, NH);
        flash_wmma_kernel<<<grid, 128>>>(x, gate_w);
    }
    // 4) output projection
    {
        dim3 grid(1024 / 128, 2048 / 64);
        gemm_presplit_kernel<1><<<grid, 128>>>(out, TT, DD, DD);
    }
}

// round 12
// speedup vs baseline: 1.1782x; 1.1782x over previous
#include <cuda_runtime.h>
#include <cuda_fp16.h>
#include <cuda_pipeline.h>
#include <mma.h>
#include <math.h>

using namespace nvcuda;

#define TT 2048
#define DD 1024
#define NH 8
#define HD 128
#define GATE_IN 12

#define ATTN_SCALE 0.12f
#define RMS_EPS 1e-6f
#define LOG2E 1.4426950408889634f
#define SOFT_SHIFT 8.0f

static __device__ float  g_qkv[(size_t)TT * 3 * DD];  // [t][3*D]
static __device__ __half g_wh[(size_t)4 * DD * DD];   // weight hi
static __device__ __half g_wl[(size_t)4 * DD * DD];   // weight lo
static __device__ __half g_xh[(size_t)TT * DD];       // x hi
static __device__ __half g_xl[(size_t)TT * DD];       // x lo
static __device__ __half g_yh[(size_t)TT * DD];       // y hi
static __device__ __half g_yl[(size_t)TT * DD];       // y lo
static __device__ __half g_qh[(size_t)NH * TT * HD];  // scaled q hi
static __device__ __half g_ql[(size_t)NH * TT * HD];  // scaled q lo
static __device__ __half g_kh[(size_t)NH * TT * HD];  // k hi
static __device__ __half g_kl[(size_t)NH * TT * HD];  // k lo
static __device__ __half g_vh[(size_t)NH * TT * HD];  // v half

// ---------------------------------------------------------------------------
// split f32 -> (hi, lo) f16 pairs for both w and x in one launch.
// ---------------------------------------------------------------------------
__device__ __forceinline__ void split4(const float* __restrict__ src, size_t i,
                                       __half* __restrict__ dh,
                                       __half* __restrict__ dl)
{
    float4 v = ((const float4*)src)[i];
    __half h0 = __float2half_rn(v.x), h1 = __float2half_rn(v.y);
    __half h2 = __float2half_rn(v.z), h3 = __float2half_rn(v.w);
    __half2* dh2 = (__half2*)dh;
    __half2* dl2 = (__half2*)dl;
    dh2[i * 2]     = __halves2half2(h0, h1);
    dh2[i * 2 + 1] = __halves2half2(h2, h3);
    dl2[i * 2]     = __halves2half2(__float2half_rn(v.x - __half2float(h0)),
                                    __float2half_rn(v.y - __half2float(h1)));
    dl2[i * 2 + 1] = __halves2half2(__float2half_rn(v.z - __half2float(h2)),
                                    __float2half_rn(v.w - __half2float(h3)));
}

#define WCHUNKS (4 * DD * DD / 4)
#define XCHUNKS (TT * DD / 4)

__global__ void split_all_kernel(const float* __restrict__ w,
                                 const float* __restrict__ x)
{
    size_t i = (size_t)blockIdx.x * blockDim.x + threadIdx.x;
    if (i < WCHUNKS) {
        split4(w, i, g_wh, g_wl);
    } else {
        split4(x, i - WCHUNKS, g_xh, g_xl);
    }
}

// ---------------------------------------------------------------------------
// f16x3 GEMM on pre-split halves, 2-stage cp.async pipeline (round-11,
// measured good). Block 64x128, BK=16, 128 thr = 4 warps (2x2; tile 32x64).
// MODE 0: A = g_xh/g_xl, B = W[0:3D], C = g_qkv.
// MODE 1: A = g_yh/g_yl, B = W[3D:4D], C = out.
// ---------------------------------------------------------------------------
template <int MODE>
__global__ void __launch_bounds__(128) gemm_presplit_kernel(
    float* __restrict__ Cext, int M, int N, int K)
{
    const __half* __restrict__ Ahp = (MODE == 0) ? g_xh : g_yh;
    const __half* __restrict__ Alp = (MODE == 0) ? g_xl : g_yl;
    const __half* __restrict__ Bhp = g_wh + (MODE == 0 ? 0 : (size_t)3 * DD * DD);
    const __half* __restrict__ Blp = g_wl + (MODE == 0 ? 0 : (size_t)3 * DD * DD);
    float* __restrict__ C = (MODE == 0) ? (float*)g_qkv : Cext;

    __shared__ __half Ah[2][64][24];
    __shared__ __half Al[2][64][24];
    __shared__ __half Bh[2][128][24];
    __shared__ __half Bl[2][128][24];

    const int tid = threadIdx.x;
    const int warp = tid >> 5;
    const int wm = warp >> 1;       // 0..1
    const int wn = warp & 1;        // 0..1
    const int bm = blockIdx.y * 64, bn = blockIdx.x * 128;

    const int arr = tid >> 1, ac8 = (tid & 1) * 8;

    wmma::fragment<wmma::accumulator, 16, 16, 16, float> acc[2][4];
#pragma unroll
    for (int mt = 0; mt < 2; mt++)
#pragma unroll
        for (int nt = 0; nt < 4; nt++)
            wmma::fill_fragment(acc[mt][nt], 0.0f);

    const int nk = K / 16;

    // prologue: stage 0
    {
        size_t go = (size_t)(bm + arr) * K + ac8;
        __pipeline_memcpy_async(&Ah[0][arr][ac8], Ahp + go, 16);
        __pipeline_memcpy_async(&Al[0][arr][ac8], Alp + go, 16);
#pragma unroll
        for (int i = 0; i < 2; i++) {
            int idx = tid + i * 128;
            int rr = idx >> 1, c8 = (idx & 1) * 8;
            size_t gob = (size_t)(bn + rr) * K + c8;
            __pipeline_memcpy_async(&Bh[0][rr][c8], Bhp + gob, 16);
            __pipeline_memcpy_async(&Bl[0][rr][c8], Blp + gob, 16);
        }
        __pipeline_commit();
    }

    for (int it = 0; it < nk; it++) {
        if (it + 1 < nk) {
            const int s = (it + 1) & 1;
            const int kt = (it + 1) * 16;
            size_t go = (size_t)(bm + arr) * K + kt + ac8;
            __pipeline_memcpy_async(&Ah[s][arr][ac8], Ahp + go, 16);
            __pipeline_memcpy_async(&Al[s][arr][ac8], Alp + go, 16);
#pragma unroll
            for (int i = 0; i < 2; i++) {
                int idx = tid + i * 128;
                int rr = idx >> 1, c8 = (idx & 1) * 8;
                size_t gob = (size_t)(bn + rr) * K + kt + c8;
                __pipeline_memcpy_async(&Bh[s][rr][c8], Bhp + gob, 16);
                __pipeline_memcpy_async(&Bl[s][rr][c8], Blp + gob, 16);
            }
            __pipeline_commit();
            __pipeline_wait_prior(1);
        } else {
            __pipeline_wait_prior(0);
        }
        __syncthreads();

        const int s = it & 1;
        wmma::fragment<wmma::matrix_a, 16, 16, 16, __half,
                       wmma::row_major> fah[2], fal[2];
#pragma unroll
        for (int mt = 0; mt < 2; mt++) {
            wmma::load_matrix_sync(fah[mt], &Ah[s][wm * 32 + mt * 16][0], 24);
            wmma::load_matrix_sync(fal[mt], &Al[s][wm * 32 + mt * 16][0], 24);
        }
#pragma unroll
        for (int nt = 0; nt < 4; nt++) {
            wmma::fragment<wmma::matrix_b, 16, 16, 16, __half,
                           wmma::col_major> fbh, fbl;
            wmma::load_matrix_sync(fbh, &Bh[s][wn * 64 + nt * 16][0], 24);
            wmma::load_matrix_sync(fbl, &Bl[s][wn * 64 + nt * 16][0], 24);
#pragma unroll
            for (int mt = 0; mt < 2; mt++) {
                wmma::mma_sync(acc[mt][nt], fah[mt], fbh, acc[mt][nt]);
                wmma::mma_sync(acc[mt][nt], fal[mt], fbh, acc[mt][nt]);
                wmma::mma_sync(acc[mt][nt], fah[mt], fbl, acc[mt][nt]);
            }
        }
        __syncthreads();
    }

#pragma unroll
    for (int mt = 0; mt < 2; mt++)
#pragma unroll
        for (int nt = 0; nt < 4; nt++) {
            float* cp = C + (size_t)(bm + wm * 32 + mt * 16) * N
                          + bn + wn * 64 + nt * 16;
            wmma::store_matrix_sync(cp, acc[mt][nt], N, wmma::mem_row_major);
        }
}

// ---------------------------------------------------------------------------
// Postprocess: per (t,h): rms_norm + rotary on q,k; v = l0*v + l1*ve.
// Emits pre-scaled f16 hi/lo splits for q (scale*log2e folded) and k, v half.
// ---------------------------------------------------------------------------
__global__ void postproc_kernel(const float* __restrict__ ve,
                                const float* __restrict__ lam,
                                const float* __restrict__ cosb,
                                const float* __restrict__ sinb)
{
    const int t = blockIdx.x >> 3;
    const int h = blockIdx.x & 7;
    const int hd = threadIdx.x;

    const float* rowp = g_qkv + (size_t)t * (3 * DD) + h * HD;
    float qv = rowp[hd];
    float kv = rowp[DD + hd];
    float vv = rowp[2 * DD + hd];

    float sq = qv * qv, sk = kv * kv;
#pragma unroll
    for (int o = 16; o; o >>= 1) {
        sq += __shfl_xor_sync(0xffffffffu, sq, o);
        sk += __shfl_xor_sync(0xffffffffu, sk, o);
    }
    __shared__ float red[2][4];
    int w = hd >> 5, lane = hd & 31;
    if (lane == 0) { red[0][w] = sq; red[1][w] = sk; }
    __syncthreads();
    sq = red[0][0] + red[0][1] + red[0][2] + red[0][3];
    sk = red[1][0] + red[1][1] + red[1][2] + red[1][3];
    float qr = rsqrtf(sq * (1.0f / HD) + RMS_EPS);
    float kr = rsqrtf(sk * (1.0f / HD) + RMS_EPS);

    __shared__ float qn[HD], kn[HD];
    qn[hd] = qv * qr;
    kn[hd] = kv * kr;
    __syncthreads();

    float qo, ko;
    if (hd < 64) {
        float cc = cosb[t * 64 + hd];
        float ss = sinb[t * 64 + hd];
        qo = qn[hd] * cc + qn[hd + 64] * ss;
        ko = kn[hd] * cc + kn[hd + 64] * ss;
    } else {
        int j = hd - 64;
        float cc = cosb[t * 64 + j];
        float ss = sinb[t * 64 + j];
        qo = -qn[j] * ss + qn[hd] * cc;
        ko = -kn[j] * ss + kn[hd] * cc;
    }
    const float lm0 = __ldg(lam);
    const float lm1 = __ldg(lam + 1);
    size_t oidx = ((size_t)h * TT + t) * HD + hd;

    float qs = qo * (ATTN_SCALE * LOG2E);
    __half qhh = __float2half_rn(qs);
    g_qh[oidx] = qhh;
    g_ql[oidx] = __float2half_rn(qs - __half2float(qhh));
    __half khh = __float2half_rn(ko);
    g_kh[oidx] = khh;
    g_kl[oidx] = __float2half_rn(ko - __half2float(khh));
    float vo = lm0 * vv + lm1 * ve[((size_t)t * NH + h) * HD + hd];
    g_vh[oidx] = __float2half_rn(vo);
}

// ---------------------------------------------------------------------------
// Flash attention, all-f16 wmma — byte-identical mainloop to the round-10
// version (measured good: synchronous tile loads, 2 syncs/tile).
// Epilogue emits y as (hi, lo) halves for the pre-split O-projection.
// ---------------------------------------------------------------------------
__global__ void __launch_bounds__(128) flash_wmma_kernel(
    const float* __restrict__ x, const float* __restrict__ gate_w)
{
    __shared__ __align__(16) unsigned char smraw[40448];
    __half (*Khs)[136] = (__half (*)[136])(smraw);
    __half (*Kls)[136] = (__half (*)[136])(smraw + 8704);
    __half (*Vsm)[136] = (__half (*)[136])(smraw + 17408);

    const int h = blockIdx.y;
    const int qb = (int)gridDim.x - 1 - (int)blockIdx.x;   // heavy tiles first
    const int tid = threadIdx.x, warp = tid >> 5, lane = tid & 31;
    const int qbase = qb * 64;
    const int wrow0 = qbase + warp * 16;
    const int myrow = lane >> 1;
    const int myhalf = lane & 1;
    const int grow = wrow0 + myrow;

    float  (*Ssm_w)[36] = (float  (*)[36])(smraw + 26112 + warp * 2304);
    __half (*Psm_w)[40] = (__half (*)[40])(smraw + 35328 + warp * 1280);

    const __half* Qhp = g_qh + (size_t)h * TT * HD;
    const __half* Qlp = g_ql + (size_t)h * TT * HD;
    const __half* Khp = g_kh + (size_t)h * TT * HD;
    const __half* Klp = g_kl + (size_t)h * TT * HD;
    const __half* Vp  = g_vh + (size_t)h * TT * HD;

    wmma::fragment<wmma::matrix_a, 16, 16, 16, __half, wmma::row_major> qhf[8];
#pragma unroll
    for (int kt = 0; kt < 8; kt++)
        wmma::load_matrix_sync(qhf[kt], Qhp + (size_t)wrow0 * HD + kt * 16, HD);

    wmma::fragment<wmma::accumulator, 16, 16, 16, float> oacc[8];
#pragma unroll
    for (int nt = 0; nt < 8; nt++) wmma::fill_fragment(oacc[nt], 0.0f);
    float lrun = 0.0f;

    const int nkb = 2 * qb + 2;
    for (int kb = 0; kb < nkb; kb++) {
        const int kbase = kb * 32;
        __syncthreads();
#pragma unroll
        for (int i = 0; i < 4; i++) {
            int idx = tid + i * 128;
            int rr = idx >> 4;
            int c8 = (idx & 15) * 8;
            size_t goff = (size_t)(kbase + rr) * HD + c8;
            *(float4*)&Khs[rr][c8] = *(const float4*)(Khp + goff);
            *(float4*)&Kls[rr][c8] = *(const float4*)(Klp + goff);
            *(float4*)&Vsm[rr][c8] = *(const float4*)(Vp + goff);
        }
        __syncthreads();

        const bool active = (kbase <= wrow0 + 15);   // warp-uniform
        if (active) {
            wmma::fragment<wmma::accumulator, 16, 16, 16, float> sacc[2];
            wmma::fill_fragment(sacc[0], 0.0f);
            wmma::fill_fragment(sacc[1], 0.0f);
#pragma unroll
            for (int kt = 0; kt < 8; kt++) {
                wmma::fragment<wmma::matrix_a, 16, 16, 16, __half,
                               wmma::row_major> qlf;
                wmma::load_matrix_sync(qlf, Qlp + (size_t)wrow0 * HD + kt * 16, HD);
#pragma unroll
                for (int nt = 0; nt < 2; nt++) {
                    wmma::fragment<wmma::matrix_b, 16, 16, 16, __half,
                                   wmma::col_major> khf, klf;
                    wmma::load_matrix_sync(khf, &Khs[nt * 16][kt * 16], 136);
                    wmma::load_matrix_sync(klf, &Kls[nt * 16][kt * 16], 136);
                    wmma::mma_sync(sacc[nt], qhf[kt], khf, sacc[nt]);
                    wmma::mma_sync(sacc[nt], qlf,     khf, sacc[nt]);
                    wmma::mma_sync(sacc[nt], qhf[kt], klf, sacc[nt]);
                }
            }
            wmma::store_matrix_sync(&Ssm_w[0][0],  sacc[0], 36, wmma::mem_row_major);
            wmma::store_matrix_sync(&Ssm_w[0][16], sacc[1], 36, wmma::mem_row_major);
        }
        __syncwarp();
        if (active) {
            float lsum = 0.0f;
#pragma unroll
            for (int j = 0; j < 16; j++) {
                int col = myhalf * 16 + j;
                int gcol = kbase + col;
                float sv = Ssm_w[myrow][col];
                float p = (gcol <= grow) ? exp2f(sv - SOFT_SHIFT) : 0.0f;
                lsum += p;
                Psm_w[myrow][col] = __float2half(p);
            }
            lsum += __shfl_xor_sync(0xffffffffu, lsum, 1);
            lrun += lsum;
        }
        __syncwarp();
        if (active) {
#pragma unroll
            for (int ks = 0; ks < 2; ks++) {
                wmma::fragment<wmma::matrix_a, 16, 16, 16,
                               __half, wmma::row_major> pfrag;
                wmma::load_matrix_sync(pfrag, &Psm_w[0][ks * 16], 40);
#pragma unroll
                for (int nt = 0; nt < 8; nt++) {
                    wmma::fragment<wmma::matrix_b, 16, 16, 16,
                                   __half, wmma::row_major> vfrag;
                    wmma::load_matrix_sync(vfrag, &Vsm[ks * 16][nt * 16], 136);
                    wmma::mma_sync(oacc[nt], pfrag, vfrag, oacc[nt]);
                }
            }
        }
    }

    // epilogue: stage O to smem, normalize, gate, emit (hi, lo) halves
    __syncthreads();
    float (*Osm_w)[132] = (float (*)[132])(smraw + warp * 8448);
#pragma unroll
    for (int nt = 0; nt < 8; nt++)
        wmma::store_matrix_sync(&Osm_w[0][nt * 16], oacc[nt], 132,
                                wmma::mem_row_major);
    __syncwarp();

    float gd = 0.0f;
#pragma unroll
    for (int i = 0; i < GATE_IN; i++)
        gd += x[(size_t)grow * DD + i] * gate_w[h * GATE_IN + i];
    float gate = 1.0f / (1.0f + expf(-gd));
    float scale = gate / lrun;

    const int c0 = myhalf * 64;
    __half* yh = g_yh + (size_t)grow * DD + h * HD;
    __half* yl = g_yl + (size_t)grow * DD + h * HD;
#pragma unroll
    for (int j = 0; j < 16; j++) {
        float4 ov = *(float4*)&Osm_w[myrow][c0 + j * 4];
        float v0 = ov.x * scale, v1 = ov.y * scale;
        float v2 = ov.z * scale, v3 = ov.w * scale;
        __half h0 = __float2half_rn(v0), h1 = __float2half_rn(v1);
        __half h2 = __float2half_rn(v2), h3 = __float2half_rn(v3);
        __half2* yh2 = (__half2*)(yh + c0 + j * 4);
        yh2[0] = __halves2half2(h0, h1);
        yh2[1] = __halves2half2(h2, h3);
        __half2* yl2 = (__half2*)(yl + c0 + j * 4);
        yl2[0] = __halves2half2(__float2half_rn(v0 - __half2float(h0)),
                                __float2half_rn(v1 - __half2float(h1)));
        yl2[1] = __halves2half2(__float2half_rn(v2 - __half2float(h2)),
                                __float2half_rn(v3 - __half2float(h3)));
    }
}

// ---------------------------------------------------------------------------
extern "C" void kernel_launch(void* const* d_in, const int* in_sizes, int n_in,
                              void* d_out, int out_size)
{
    const float* x      = (const float*)d_in[0];  // (1,2048,1024)
    const float* qkvo_w = (const float*)d_in[1];  // (4,1024,1024)
    const float* gate_w = (const float*)d_in[2];  // (8,12)
    const float* ve     = (const float*)d_in[3];  // (1,2048,8,128)
    const float* lam    = (const float*)d_in[4];  // (2,)
    const float* cosb   = (const float*)d_in[5];  // (2048,64)
    const float* sinb   = (const float*)d_in[6];  // (2048,64)
    float* out = (float*)d_out;                   // (1,2048,1024)

    // 0) pre-split weights and x into f16 (hi, lo) in one launch
    split_all_kernel<<<(WCHUNKS + XCHUNKS) / 256, 256>>>(qkvo_w, x);

    // 1) QKV projection -> g_qkv
    {
        dim3 grid(3072 / 128, 2048 / 64);
        gemm_presplit_kernel<0><<<grid, 128>>>(nullptr, TT, 3 * DD, DD);
    }
    // 2) rms_norm + rotary + value mix + split
    postproc_kernel<<<TT * NH, 128>>>(ve, lam, cosb, sinb);
    // 3) causal flash attention + gate -> g_yh/g_yl
    {
        dim3 grid(TT / 64, NH);
        flash_wmma_kernel<<<grid, 128>>>(x, gate_w);
    }
    // 4) output projection
    {
        dim3 grid(1024 / 128, 2048 / 64);
        gemm_presplit_kernel<1><<<grid, 128>>>(out, TT, DD, DD);
    }
}

// round 13
// speedup vs baseline: 1.4163x; 1.2021x over previous
#include <cuda_runtime.h>
#include <cuda_fp16.h>
#include <cuda_pipeline.h>
#include <mma.h>
#include <math.h>

using namespace nvcuda;

#define TT 2048
#define DD 1024
#define NH 8
#define HD 128
#define GATE_IN 12

#define ATTN_SCALE 0.12f
#define RMS_EPS 1e-6f
#define LOG2E 1.4426950408889634f
#define SOFT_SHIFT 8.0f

#define KC 256                 // keys per split-K chunk
#define NQT (TT / 64)          // 32 q-tiles
#define MAXC 8                 // max chunks per q-tile (qt/4 + 1 <= 8)
#define CHUNKS_PER_HEAD 144    // sum over qt of (qt/4 + 1)

static __device__ float  g_qkv[(size_t)TT * 3 * DD];  // [t][3*D]
static __device__ __half g_wh[(size_t)4 * DD * DD];   // weight hi
static __device__ __half g_wl[(size_t)4 * DD * DD];   // weight lo
static __device__ __half g_xh[(size_t)TT * DD];       // x hi
static __device__ __half g_xl[(size_t)TT * DD];       // x lo
static __device__ __half g_yh[(size_t)TT * DD];       // y hi
static __device__ __half g_yl[(size_t)TT * DD];       // y lo
static __device__ __half g_qh[(size_t)NH * TT * HD];  // scaled q hi
static __device__ __half g_ql[(size_t)NH * TT * HD];  // scaled q lo
static __device__ __half g_kh[(size_t)NH * TT * HD];  // k hi
static __device__ __half g_kl[(size_t)NH * TT * HD];  // k lo
static __device__ __half g_vh[(size_t)NH * TT * HD];  // v half
// split-K partials: slot = (h*NQT + qt)*MAXC + c ; each slot 64x128 f32
static __device__ float  g_part[(size_t)NH * NQT * MAXC * 64 * 128];
static __device__ float  g_lpart[(size_t)NH * NQT * MAXC * 64];

// ---------------------------------------------------------------------------
// split f32 -> (hi, lo) f16 pairs for both w and x in one launch.
// ---------------------------------------------------------------------------
__device__ __forceinline__ void split4(const float* __restrict__ src, size_t i,
                                       __half* __restrict__ dh,
                                       __half* __restrict__ dl)
{
    float4 v = ((const float4*)src)[i];
    __half h0 = __float2half_rn(v.x), h1 = __float2half_rn(v.y);
    __half h2 = __float2half_rn(v.z), h3 = __float2half_rn(v.w);
    __half2* dh2 = (__half2*)dh;
    __half2* dl2 = (__half2*)dl;
    dh2[i * 2]     = __halves2half2(h0, h1);
    dh2[i * 2 + 1] = __halves2half2(h2, h3);
    dl2[i * 2]     = __halves2half2(__float2half_rn(v.x - __half2float(h0)),
                                    __float2half_rn(v.y - __half2float(h1)));
    dl2[i * 2 + 1] = __halves2half2(__float2half_rn(v.z - __half2float(h2)),
                                    __float2half_rn(v.w - __half2float(h3)));
}

#define WCHUNKS (4 * DD * DD / 4)
#define XCHUNKS (TT * DD / 4)

__global__ void split_all_kernel(const float* __restrict__ w,
                                 const float* __restrict__ x)
{
    size_t i = (size_t)blockIdx.x * blockDim.x + threadIdx.x;
    if (i < WCHUNKS) {
        split4(w, i, g_wh, g_wl);
    } else {
        split4(x, i - WCHUNKS, g_xh, g_xl);
    }
}

// ---------------------------------------------------------------------------
// f16x3 GEMM on pre-split halves, 2-stage cp.async pipeline (measured good).
// Block 64x128, BK=16, 128 thr = 4 warps (2x2; tile 32x64).
// MODE 0: A = g_xh/g_xl, B = W[0:3D], C = g_qkv.
// MODE 1: A = g_yh/g_yl, B = W[3D:4D], C = out.
// ---------------------------------------------------------------------------
template <int MODE>
__global__ void __launch_bounds__(128) gemm_presplit_kernel(
    float* __restrict__ Cext, int M, int N, int K)
{
    const __half* __restrict__ Ahp = (MODE == 0) ? g_xh : g_yh;
    const __half* __restrict__ Alp = (MODE == 0) ? g_xl : g_yl;
    const __half* __restrict__ Bhp = g_wh + (MODE == 0 ? 0 : (size_t)3 * DD * DD);
    const __half* __restrict__ Blp = g_wl + (MODE == 0 ? 0 : (size_t)3 * DD * DD);
    float* __restrict__ C = (MODE == 0) ? (float*)g_qkv : Cext;

    __shared__ __half Ah[2][64][24];
    __shared__ __half Al[2][64][24];
    __shared__ __half Bh[2][128][24];
    __shared__ __half Bl[2][128][24];

    const int tid = threadIdx.x;
    const int warp = tid >> 5;
    const int wm = warp >> 1;
    const int wn = warp & 1;
    const int bm = blockIdx.y * 64, bn = blockIdx.x * 128;

    const int arr = tid >> 1, ac8 = (tid & 1) * 8;

    wmma::fragment<wmma::accumulator, 16, 16, 16, float> acc[2][4];
#pragma unroll
    for (int mt = 0; mt < 2; mt++)
#pragma unroll
        for (int nt = 0; nt < 4; nt++)
            wmma::fill_fragment(acc[mt][nt], 0.0f);

    const int nk = K / 16;

    {
        size_t go = (size_t)(bm + arr) * K + ac8;
        __pipeline_memcpy_async(&Ah[0][arr][ac8], Ahp + go, 16);
        __pipeline_memcpy_async(&Al[0][arr][ac8], Alp + go, 16);
#pragma unroll
        for (int i = 0; i < 2; i++) {
            int idx = tid + i * 128;
            int rr = idx >> 1, c8 = (idx & 1) * 8;
            size_t gob = (size_t)(bn + rr) * K + c8;
            __pipeline_memcpy_async(&Bh[0][rr][c8], Bhp + gob, 16);
            __pipeline_memcpy_async(&Bl[0][rr][c8], Blp + gob, 16);
        }
        __pipeline_commit();
    }

    for (int it = 0; it < nk; it++) {
        if (it + 1 < nk) {
            const int s = (it + 1) & 1;
            const int kt = (it + 1) * 16;
            size_t go = (size_t)(bm + arr) * K + kt + ac8;
            __pipeline_memcpy_async(&Ah[s][arr][ac8], Ahp + go, 16);
            __pipeline_memcpy_async(&Al[s][arr][ac8], Alp + go, 16);
#pragma unroll
            for (int i = 0; i < 2; i++) {
                int idx = tid + i * 128;
                int rr = idx >> 1, c8 = (idx & 1) * 8;
                size_t gob = (size_t)(bn + rr) * K + kt + c8;
                __pipeline_memcpy_async(&Bh[s][rr][c8], Bhp + gob, 16);
                __pipeline_memcpy_async(&Bl[s][rr][c8], Blp + gob, 16);
            }
            __pipeline_commit();
            __pipeline_wait_prior(1);
        } else {
            __pipeline_wait_prior(0);
        }
        __syncthreads();

        const int s = it & 1;
        wmma::fragment<wmma::matrix_a, 16, 16, 16, __half,
                       wmma::row_major> fah[2], fal[2];
#pragma unroll
        for (int mt = 0; mt < 2; mt++) {
            wmma::load_matrix_sync(fah[mt], &Ah[s][wm * 32 + mt * 16][0], 24);
            wmma::load_matrix_sync(fal[mt], &Al[s][wm * 32 + mt * 16][0], 24);
        }
#pragma unroll
        for (int nt = 0; nt < 4; nt++) {
            wmma::fragment<wmma::matrix_b, 16, 16, 16, __half,
                           wmma::col_major> fbh, fbl;
            wmma::load_matrix_sync(fbh, &Bh[s][wn * 64 + nt * 16][0], 24);
            wmma::load_matrix_sync(fbl, &Bl[s][wn * 64 + nt * 16][0], 24);
#pragma unroll
            for (int mt = 0; mt < 2; mt++) {
                wmma::mma_sync(acc[mt][nt], fah[mt], fbh, acc[mt][nt]);
                wmma::mma_sync(acc[mt][nt], fal[mt], fbh, acc[mt][nt]);
                wmma::mma_sync(acc[mt][nt], fah[mt], fbl, acc[mt][nt]);
            }
        }
        __syncthreads();
    }

#pragma unroll
    for (int mt = 0; mt < 2; mt++)
#pragma unroll
        for (int nt = 0; nt < 4; nt++) {
            float* cp = C + (size_t)(bm + wm * 32 + mt * 16) * N
                          + bn + wn * 64 + nt * 16;
            wmma::store_matrix_sync(cp, acc[mt][nt], N, wmma::mem_row_major);
        }
}

// ---------------------------------------------------------------------------
// Postprocess: per (t,h): rms_norm + rotary on q,k; v = l0*v + l1*ve.
// Emits pre-scaled f16 hi/lo splits for q (scale*log2e folded) and k, v half.
// ---------------------------------------------------------------------------
__global__ void postproc_kernel(const float* __restrict__ ve,
                                const float* __restrict__ lam,
                                const float* __restrict__ cosb,
                                const float* __restrict__ sinb)
{
    const int t = blockIdx.x >> 3;
    const int h = blockIdx.x & 7;
    const int hd = threadIdx.x;

    const float* rowp = g_qkv + (size_t)t * (3 * DD) + h * HD;
    float qv = rowp[hd];
    float kv = rowp[DD + hd];
    float vv = rowp[2 * DD + hd];

    float sq = qv * qv, sk = kv * kv;
#pragma unroll
    for (int o = 16; o; o >>= 1) {
        sq += __shfl_xor_sync(0xffffffffu, sq, o);
        sk += __shfl_xor_sync(0xffffffffu, sk, o);
    }
    __shared__ float red[2][4];
    int w = hd >> 5, lane = hd & 31;
    if (lane == 0) { red[0][w] = sq; red[1][w] = sk; }
    __syncthreads();
    sq = red[0][0] + red[0][1] + red[0][2] + red[0][3];
    sk = red[1][0] + red[1][1] + red[1][2] + red[1][3];
    float qr = rsqrtf(sq * (1.0f / HD) + RMS_EPS);
    float kr = rsqrtf(sk * (1.0f / HD) + RMS_EPS);

    __shared__ float qn[HD], kn[HD];
    qn[hd] = qv * qr;
    kn[hd] = kv * kr;
    __syncthreads();

    float qo, ko;
    if (hd < 64) {
        float cc = cosb[t * 64 + hd];
        float ss = sinb[t * 64 + hd];
        qo = qn[hd] * cc + qn[hd + 64] * ss;
        ko = kn[hd] * cc + kn[hd + 64] * ss;
    } else {
        int j = hd - 64;
        float cc = cosb[t * 64 + j];
        float ss = sinb[t * 64 + j];
        qo = -qn[j] * ss + qn[hd] * cc;
        ko = -kn[j] * ss + kn[hd] * cc;
    }
    const float lm0 = __ldg(lam);
    const float lm1 = __ldg(lam + 1);
    size_t oidx = ((size_t)h * TT + t) * HD + hd;

    float qs = qo * (ATTN_SCALE * LOG2E);
    __half qhh = __float2half_rn(qs);
    g_qh[oidx] = qhh;
    g_ql[oidx] = __float2half_rn(qs - __half2float(qhh));
    __half khh = __float2half_rn(ko);
    g_kh[oidx] = khh;
    g_kl[oidx] = __float2half_rn(ko - __half2float(khh));
    float vo = lm0 * vv + lm1 * ve[((size_t)t * NH + h) * HD + hd];
    g_vh[oidx] = __float2half_rn(vo);
}

// ---------------------------------------------------------------------------
// Split-K flash attention. Grid (CHUNKS_PER_HEAD, NH), 128 threads = 4 warps.
// Block = (head h, q-tile qt of 64 rows, key chunk c of <=256 keys).
// Fixed-shift softmax makes partials exactly additive: block writes
// unnormalized O (64x128 f32) and per-row l to g_part/g_lpart.
// Mainloop per k-tile identical to the measured-good round-12 version.
// ---------------------------------------------------------------------------
__global__ void __launch_bounds__(128) flash_split_kernel()
{
    __shared__ __align__(16) unsigned char smraw[40448];
    __half (*Khs)[136] = (__half (*)[136])(smraw);
    __half (*Kls)[136] = (__half (*)[136])(smraw + 8704);
    __half (*Vsm)[136] = (__half (*)[136])(smraw + 17408);

    const int h = blockIdx.y;
    // decode flat chunk id -> (qt, c)
    int flat = blockIdx.x;
    int qt = 0;
#pragma unroll
    for (int j = 0; j < NQT; j++) {
        int nc = (j >> 2) + 1;
        if (flat < nc) { qt = j; break; }
        flat -= nc;
    }
    const int c = flat;

    const int tid = threadIdx.x, warp = tid >> 5, lane = tid & 31;
    const int qbase = qt * 64;
    const int wrow0 = qbase + warp * 16;
    const int myrow = lane >> 1;
    const int myhalf = lane & 1;
    const int grow = wrow0 + myrow;

    const int k0 = c * KC;
    const int kend = min(k0 + KC, qbase + 64);
    const int ntiles = (kend - k0) >> 5;

    float  (*Ssm_w)[36] = (float  (*)[36])(smraw + 26112 + warp * 2304);
    __half (*Psm_w)[40] = (__half (*)[40])(smraw + 35328 + warp * 1280);

    const __half* Qhp = g_qh + (size_t)h * TT * HD;
    const __half* Qlp = g_ql + (size_t)h * TT * HD;
    const __half* Khp = g_kh + (size_t)h * TT * HD;
    const __half* Klp = g_kl + (size_t)h * TT * HD;
    const __half* Vp  = g_vh + (size_t)h * TT * HD;

    wmma::fragment<wmma::matrix_a, 16, 16, 16, __half, wmma::row_major> qhf[8];
#pragma unroll
    for (int kt = 0; kt < 8; kt++)
        wmma::load_matrix_sync(qhf[kt], Qhp + (size_t)wrow0 * HD + kt * 16, HD);

    wmma::fragment<wmma::accumulator, 16, 16, 16, float> oacc[8];
#pragma unroll
    for (int nt = 0; nt < 8; nt++) wmma::fill_fragment(oacc[nt], 0.0f);
    float lrun = 0.0f;

    for (int kb = 0; kb < ntiles; kb++) {
        const int kbase = k0 + kb * 32;
        __syncthreads();
#pragma unroll
        for (int i = 0; i < 4; i++) {
            int idx = tid + i * 128;
            int rr = idx >> 4;
            int c8 = (idx & 15) * 8;
            size_t goff = (size_t)(kbase + rr) * HD + c8;
            *(float4*)&Khs[rr][c8] = *(const float4*)(Khp + goff);
            *(float4*)&Kls[rr][c8] = *(const float4*)(Klp + goff);
            *(float4*)&Vsm[rr][c8] = *(const float4*)(Vp + goff);
        }
        __syncthreads();

        const bool active = (kbase <= wrow0 + 15);   // warp-uniform
        if (active) {
            wmma::fragment<wmma::accumulator, 16, 16, 16, float> sacc[2];
            wmma::fill_fragment(sacc[0], 0.0f);
            wmma::fill_fragment(sacc[1], 0.0f);
#pragma unroll
            for (int kt = 0; kt < 8; kt++) {
                wmma::fragment<wmma::matrix_a, 16, 16, 16, __half,
                               wmma::row_major> qlf;
                wmma::load_matrix_sync(qlf, Qlp + (size_t)wrow0 * HD + kt * 16, HD);
#pragma unroll
                for (int nt = 0; nt < 2; nt++) {
                    wmma::fragment<wmma::matrix_b, 16, 16, 16, __half,
                                   wmma::col_major> khf, klf;
                    wmma::load_matrix_sync(khf, &Khs[nt * 16][kt * 16], 136);
                    wmma::load_matrix_sync(klf, &Kls[nt * 16][kt * 16], 136);
                    wmma::mma_sync(sacc[nt], qhf[kt], khf, sacc[nt]);
                    wmma::mma_sync(sacc[nt], qlf,     khf, sacc[nt]);
                    wmma::mma_sync(sacc[nt], qhf[kt], klf, sacc[nt]);
                }
            }
            wmma::store_matrix_sync(&Ssm_w[0][0],  sacc[0], 36, wmma::mem_row_major);
            wmma::store_matrix_sync(&Ssm_w[0][16], sacc[1], 36, wmma::mem_row_major);
        }
        __syncwarp();
        if (active) {
            float lsum = 0.0f;
#pragma unroll
            for (int j = 0; j < 16; j++) {
                int col = myhalf * 16 + j;
                int gcol = kbase + col;
                float sv = Ssm_w[myrow][col];
                float p = (gcol <= grow) ? exp2f(sv - SOFT_SHIFT) : 0.0f;
                lsum += p;
                Psm_w[myrow][col] = __float2half(p);
            }
            lsum += __shfl_xor_sync(0xffffffffu, lsum, 1);
            lrun += lsum;
        }
        __syncwarp();
        if (active) {
#pragma unroll
            for (int ks = 0; ks < 2; ks++) {
                wmma::fragment<wmma::matrix_a, 16, 16, 16,
                               __half, wmma::row_major> pfrag;
                wmma::load_matrix_sync(pfrag, &Psm_w[0][ks * 16], 40);
#pragma unroll
                for (int nt = 0; nt < 8; nt++) {
                    wmma::fragment<wmma::matrix_b, 16, 16, 16,
                                   __half, wmma::row_major> vfrag;
                    wmma::load_matrix_sync(vfrag, &Vsm[ks * 16][nt * 16], 136);
                    wmma::mma_sync(oacc[nt], pfrag, vfrag, oacc[nt]);
                }
            }
        }
    }

    // write partials straight to global (no normalization here)
    const size_t slot = ((size_t)h * NQT + qt) * MAXC + c;
    float* po = g_part + slot * (64 * 128) + (size_t)(warp * 16) * 128;
#pragma unroll
    for (int nt = 0; nt < 8; nt++)
        wmma::store_matrix_sync(po + nt * 16, oacc[nt], 128,
                                wmma::mem_row_major);
    if (myhalf == 0)
        g_lpart[slot * 64 + warp * 16 + myrow] = lrun;
}

// ---------------------------------------------------------------------------
// Reduce: per (qt, h), sum chunk partials, normalize with gate/l, emit yh/yl.
// Grid (NQT, NH), 128 threads; thread owns (row = tid/2, half = tid&1).
// ---------------------------------------------------------------------------
__global__ void __launch_bounds__(128) reduce_kernel(
    const float* __restrict__ x, const float* __restrict__ gate_w)
{
    const int qt = blockIdx.x, h = blockIdx.y;
    const int tid = threadIdx.x;
    const int r = tid >> 1;
    const int hf = tid & 1;
    const int grow = qt * 64 + r;
    const int nc = (qt >> 2) + 1;

    const size_t slot0 = ((size_t)h * NQT + qt) * MAXC;

    float l = 0.0f;
    for (int c = 0; c < nc; c++)
        l += g_lpart[(slot0 + c) * 64 + r];

    float gd = 0.0f;
#pragma unroll
    for (int i = 0; i < GATE_IN; i++)
        gd += x[(size_t)grow * DD + i] * gate_w[h * GATE_IN + i];
    float gate = 1.0f / (1.0f + expf(-gd));
    float scale = gate / l;

    const int c0 = hf * 64;
    __half* yh = g_yh + (size_t)grow * DD + h * HD;
    __half* yl = g_yl + (size_t)grow * DD + h * HD;
#pragma unroll
    for (int j = 0; j < 16; j++) {
        float4 acc = make_float4(0.f, 0.f, 0.f, 0.f);
        for (int c = 0; c < nc; c++) {
            const float* pp = g_part + (slot0 + c) * (64 * 128)
                            + (size_t)r * 128 + c0 + j * 4;
            float4 v = *(const float4*)pp;
            acc.x += v.x; acc.y += v.y; acc.z += v.z; acc.w += v.w;
        }
        float v0 = acc.x * scale, v1 = acc.y * scale;
        float v2 = acc.z * scale, v3 = acc.w * scale;
        __half h0 = __float2half_rn(v0), h1 = __float2half_rn(v1);
        __half h2 = __float2half_rn(v2), h3 = __float2half_rn(v3);
        __half2* yh2 = (__half2*)(yh + c0 + j * 4);
        yh2[0] = __halves2half2(h0, h1);
        yh2[1] = __halves2half2(h2, h3);
        __half2* yl2 = (__half2*)(yl + c0 + j * 4);
        yl2[0] = __halves2half2(__float2half_rn(v0 - __half2float(h0)),
                                __float2half_rn(v1 - __half2float(h1)));
        yl2[1] = __halves2half2(__float2half_rn(v2 - __half2float(h2)),
                                __float2half_rn(v3 - __half2float(h3)));
    }
}

// ---------------------------------------------------------------------------
extern "C" void kernel_launch(void* const* d_in, const int* in_sizes, int n_in,
                              void* d_out, int out_size)
{
    const float* x      = (const float*)d_in[0];  // (1,2048,1024)
    const float* qkvo_w = (const float*)d_in[1];  // (4,1024,1024)
    const float* gate_w = (const float*)d_in[2];  // (8,12)
    const float* ve     = (const float*)d_in[3];  // (1,2048,8,128)
    const float* lam    = (const float*)d_in[4];  // (2,)
    const float* cosb   = (const float*)d_in[5];  // (2048,64)
    const float* sinb   = (const float*)d_in[6];  // (2048,64)
    float* out = (float*)d_out;                   // (1,2048,1024)

    // 0) pre-split weights and x into f16 (hi, lo)
    split_all_kernel<<<(WCHUNKS + XCHUNKS) / 256, 256>>>(qkvo_w, x);

    // 1) QKV projection -> g_qkv
    {
        dim3 grid(3072 / 128, 2048 / 64);
        gemm_presplit_kernel<0><<<grid, 128>>>(nullptr, TT, 3 * DD, DD);
    }
    // 2) rms_norm + rotary + value mix + split
    postproc_kernel<<<TT * NH, 128>>>(ve, lam, cosb, sinb);
    // 3) split-K causal flash attention -> partials
    {
        dim3 grid(CHUNKS_PER_HEAD, NH);
        flash_split_kernel<<<grid, 128>>>();
    }
    // 3b) reduce partials + gate -> g_yh/g_yl
    {
        dim3 grid(NQT, NH);
        reduce_kernel<<<grid, 128>>>(x, gate_w);
    }
    // 4) output projection
    {
        dim3 grid(1024 / 128, 2048 / 64);
        gemm_presplit_kernel<1><<<grid, 128>>>(out, TT, DD, DD);
    }
}